// round 4
// baseline (speedup 1.0000x reference)
#include <cuda_runtime.h>
#include <cuda_bf16.h>
#include <cstdint>

// Problem constants
#define NB   16
#define NPTS 65536
#define NPAT 64      // NUM_PATCHES
#define KNN  32      // PATCH_SIZE

// FPS decomposition: cluster of 8 CTAs per batch, 1024 threads, 8 pts/thread
#define FPS_BLKS   8
#define FPS_THR    1024
#define FPS_PPT    8

typedef unsigned long long u64;
typedef unsigned int u32;

// Scratch (allocation-free rule: __device__ global)
__device__ float4 g_pts4[NB * NPTS];   // x,y,z,|p|^2 (FMA-chain p2)

// ---------------------------------------------------------------------------
// Kernel 0: prep — pad points to float4 with p2 (vectorized).
// p2 uses the XLA/LLVM FP-contraction shape: fma(z,z, fma(y,y, x*x))
// ---------------------------------------------------------------------------
__global__ void prep_kernel(const float* __restrict__ pts) {
    int i = blockIdx.x * blockDim.x + threadIdx.x;   // 262144 threads
    const float4* in4 = (const float4*)pts;
    float4 a = in4[3 * i + 0];
    float4 b = in4[3 * i + 1];
    float4 c = in4[3 * i + 2];
    float xs[4] = {a.x, a.w, b.z, c.y};
    float ys[4] = {a.y, b.x, b.w, c.z};
    float zs[4] = {a.z, b.y, c.x, c.w};
#pragma unroll
    for (int j = 0; j < 4; j++) {
        float p2 = __fmaf_rn(zs[j], zs[j], __fmaf_rn(ys[j], ys[j], __fmul_rn(xs[j], xs[j])));
        g_pts4[4 * i + j] = make_float4(xs[j], ys[j], zs[j], p2);
    }
}

// ---- cluster helpers ----
__device__ __forceinline__ u32 smem_u32(const void* p) {
    return (u32)__cvta_generic_to_shared(p);
}
__device__ __forceinline__ u32 mapa_u32(u32 laddr, u32 rank) {
    u32 r;
    asm("mapa.shared::cluster.u32 %0, %1, %2;" : "=r"(r) : "r"(laddr), "r"(rank));
    return r;
}
__device__ __forceinline__ void st_cluster_u64(u32 addr, u64 v) {
    asm volatile("st.shared::cluster.u64 [%0], %1;" :: "r"(addr), "l"(v) : "memory");
}

// ---------------------------------------------------------------------------
// Kernel 1: FPS — one 8-CTA cluster per batch. Points + min_d in registers
// (scalar math, bit-identical to the verified round-2 arithmetic, ~55 regs).
// Per-iteration all-to-all over DSMEM: each CTA's warp-0 lanes 0-7 push the
// block-best key into all 8 CTAs' smem slots (double-buffered by parity),
// one cluster barrier (release/acquire) orders them, then a LOCAL smem
// reduce picks the winner. No L2 polling anywhere.
// ---------------------------------------------------------------------------
__global__ void __launch_bounds__(FPS_THR, 1) __cluster_dims__(FPS_BLKS, 1, 1)
fps_kernel(float* __restrict__ centers_out /* [NB][NPAT][3] */) {
    const int b    = blockIdx.y;
    const int rank = blockIdx.x;          // == cluster_ctarank, 0..7
    const int tid  = threadIdx.x;
    const int lane = tid & 31;
    const int wid  = tid >> 5;            // 0..31

    const float4* pts = g_pts4 + (size_t)b * NPTS;
    const int gbase = rank * (NPTS / FPS_BLKS);   // 8192 per CTA

    float px[FPS_PPT], py[FPS_PPT], pz[FPS_PPT], md[FPS_PPT];
#pragma unroll
    for (int j = 0; j < FPS_PPT; j++) {
        float4 p = pts[gbase + j * FPS_THR + tid];
        px[j] = p.x; py[j] = p.y; pz[j] = p.z;
        md[j] = 3.402823466e38f;   // finfo(float32).max
    }

    __shared__ float sc[4];
    __shared__ u64 wb[32];
    __shared__ u64 slots[2][FPS_BLKS];   // double-buffered peer keys

    if (tid == 0) {
        float4 c = pts[0];                // deterministic start at index 0
        sc[0] = c.x; sc[1] = c.y; sc[2] = c.z;
    }

    for (int iter = 0; iter < NPAT; iter++) {
        __syncthreads();   // sc valid
        float cx = sc[0], cy = sc[1], cz = sc[2];
        if (rank == 0 && tid == 0) {
            centers_out[(b * NPAT + iter) * 3 + 0] = cx;
            centers_out[(b * NPAT + iter) * 3 + 1] = cy;
            centers_out[(b * NPAT + iter) * 3 + 2] = cz;
        }
        if (iter == NPAT - 1) break;   // last winner never consumed

        // --- local update + argmax (exact round-2 arithmetic) ---
        float bestv = -1.0f;
        u32   besti = 0;
#pragma unroll
        for (int j = 0; j < FPS_PPT; j++) {
            float dx = px[j] - cx, dy = py[j] - cy, dz = pz[j] - cz;
            float d = __fadd_rn(__fadd_rn(__fmul_rn(dx, dx), __fmul_rn(dy, dy)), __fmul_rn(dz, dz));
            float m = fminf(md[j], d);
            md[j] = m;
            // strict > keeps the earliest (lowest-gi) maximum, matching argmax
            if (m > bestv) { bestv = m; besti = (u32)(gbase + j * FPS_THR + tid); }
        }
        // key: (float bits, ~idx) -> max picks largest d, ties -> lowest index.
        // md >= 0 so float bits are order-preserving unsigned; key always > 0.
        u64 best = ((u64)__float_as_uint(bestv) << 32) | (u32)(~besti);
#pragma unroll
        for (int off = 16; off; off >>= 1) {
            u64 o = __shfl_xor_sync(0xffffffffu, best, off);
            if (o > best) best = o;
        }
        if (lane == 0) wb[wid] = best;
        __syncthreads();

        const int p = iter & 1;
        if (wid == 0) {
            u64 v = wb[lane];
#pragma unroll
            for (int off = 16; off; off >>= 1) {
                u64 o = __shfl_xor_sync(0xffffffffu, v, off);
                if (o > v) v = o;
            }
            // xor-reduce leaves the block max in ALL lanes: lanes 0-7 each
            // push it into peer CTA 'lane''s slot for this parity.
            if (lane < FPS_BLKS) {
                u32 laddr = smem_u32(&slots[p][rank]);
                st_cluster_u64(mapa_u32(laddr, (u32)lane), v);
            }
        }
        // release-arrive orders the remote stores; wait acquires peers'.
        asm volatile("barrier.cluster.arrive.aligned;" ::: "memory");
        asm volatile("barrier.cluster.wait.aligned;"   ::: "memory");

        if (wid == 0 && lane < FPS_BLKS) {
            u64 s = slots[p][lane];
#pragma unroll
            for (int off = 4; off; off >>= 1) {
                u64 o = __shfl_xor_sync(0xffu, s, off);
                if (o > s) s = o;
            }
            if (lane == 0) {
                u32 wi = ~(u32)s;          // winning global index
                float4 c = pts[wi];        // L2-broadcast across CTAs
                sc[0] = c.x; sc[1] = c.y; sc[2] = c.z;
            }
        }
    }
}

// ---------------------------------------------------------------------------
// Kernel 2: exact KNN top-32 (UNCHANGED from round 3 — verified exact).
// 1024 threads = 32 warps = 8 centers x 4 point-quarters.
// ---------------------------------------------------------------------------
__device__ __forceinline__ u64 bsort32(u64 v, int lane) {
#pragma unroll
    for (int k = 2; k <= 32; k <<= 1) {
#pragma unroll
        for (int j = k >> 1; j > 0; j >>= 1) {
            u64 o = __shfl_xor_sync(0xffffffffu, v, j);
            bool up      = ((lane & k) == 0);
            bool keepmin = (((lane & j) == 0) == up);
            bool smaller = (v < o);
            v = (smaller == keepmin) ? v : o;
        }
    }
    return v;
}
__device__ __forceinline__ u64 bmerge32(u64 v, int lane) {
#pragma unroll
    for (int j = 16; j > 0; j >>= 1) {
        u64 o = __shfl_xor_sync(0xffffffffu, v, j);
        bool keepmin = ((lane & j) == 0);
        bool smaller = (v < o);
        v = (smaller == keepmin) ? v : o;
    }
    return v;
}
__device__ __forceinline__ u32 flipf(float f) {
    u32 u = __float_as_uint(f);
    return u ^ ((u & 0x80000000u) ? 0xFFFFFFFFu : 0x80000000u);
}

#define KNN_CH 512           // points per quarter per chunk
#define QTR    (NPTS / 4)    // 16384

__global__ void __launch_bounds__(1024, 1)
knn_kernel(const float* __restrict__ centers /* [NB][NPAT][3] */,
           float* __restrict__ patches_out   /* [NB][NPAT][KNN][3] */) {
    const int b    = blockIdx.y;      // 16
    const int grp  = blockIdx.x;      // 8 -> centers grp*8 .. grp*8+7
    const int tid  = threadIdx.x;
    const int lane = tid & 31;
    const int w    = tid >> 5;        // 0..31
    const int cl   = w & 7;           // center within group
    const int q    = w >> 3;          // quarter 0..3
    const int c    = grp * 8 + cl;

    const float4* pbase = g_pts4 + (size_t)b * NPTS;

    const float cx = centers[(b * NPAT + c) * 3 + 0];
    const float cy = centers[(b * NPAT + c) * 3 + 1];
    const float cz = centers[(b * NPAT + c) * 3 + 2];
    const float c2 = __fmaf_rn(cz, cz, __fmaf_rn(cy, cy, __fmul_rn(cx, cx)));

    u64 L = 0xFF80000000000000ull;              // key for d2=+inf, idx 0
    float curMax = __int_as_float(0x7f800000);  // +inf

    __shared__ float4 chunk[4 * KNN_CH];        // 32 KB
    __shared__ u64 smg[8][3][32];               // 6 KB quarter-merge buffers

    const int qbase = q * QTR;

    for (int cb = 0; cb < QTR; cb += KNN_CH) {
        __syncthreads();
        for (int t = tid; t < 4 * KNN_CH; t += 1024) {
            int qq = t >> 9;
            int off = t & (KNN_CH - 1);
            chunk[t] = pbase[qq * QTR + cb + off];
        }
        __syncthreads();

        const float4* my = chunk + q * KNN_CH;
        float4 p = my[lane];
        for (int i = 0; i < KNN_CH / 32; i++) {
            float4 pn;
            if (i < KNN_CH / 32 - 1) pn = my[(i + 1) * 32 + lane];
            // XLA-shape d2: fma(-2, dot, c2+p2), dot = fma chain
            float dot = __fmaf_rn(p.z, cz, __fmaf_rn(p.y, cy, __fmul_rn(p.x, cx)));
            float d2  = __fmaf_rn(-2.0f, dot, __fadd_rn(c2, p.w));
            u32 mask = __ballot_sync(0xffffffffu, d2 <= curMax);
            if (mask) {
                u32 gi = (u32)(qbase + cb + i * 32 + lane);
                u64 cand = ((u64)flipf(d2) << 32) | gi;
                if (__popc(mask) <= 8) {
                    while (mask) {
                        int src = __ffs(mask) - 1; mask &= mask - 1;
                        u64 k  = __shfl_sync(0xffffffffu, cand, src);
                        u64 up = __shfl_up_sync(0xffffffffu, L, 1);
                        if (lane == 0) up = k;
                        u64 mx = (k > up) ? k : up;
                        L = (L < k) ? L : mx;
                    }
                } else {
                    u64 cs = bsort32(cand, lane);
                    u64 o  = __shfl_sync(0xffffffffu, cs, 31 - lane);
                    u64 m  = (L < o) ? L : o;
                    L = bmerge32(m, lane);
                }
                u64 top = __shfl_sync(0xffffffffu, L, 31);
                u32 th = (u32)(top >> 32);
                th ^= (th & 0x80000000u) ? 0x80000000u : 0xFFFFFFFFu;
                curMax = __uint_as_float(th);
            }
            p = pn;
        }
    }

    // merge 4 quarters per center: (1->0, 3->2), then (2->0)
    if (q == 1) { smg[cl][0][lane] = L; }
    if (q == 3) { smg[cl][1][lane] = L; }
    __syncthreads();
    if (q == 0) { u64 o = smg[cl][0][31 - lane]; u64 m = (L < o) ? L : o; L = bmerge32(m, lane); }
    if (q == 2) { u64 o = smg[cl][1][31 - lane]; u64 m = (L < o) ? L : o; L = bmerge32(m, lane); }
    __syncthreads();
    if (q == 2) { smg[cl][2][lane] = L; }
    __syncthreads();
    if (q == 0) {
        u64 o = smg[cl][2][31 - lane]; u64 m = (L < o) ? L : o; L = bmerge32(m, lane);
        // lane == rank k: gather + subtract center
        u32 gi = (u32)L;
        float4 p = pbase[gi];
        float* dst = patches_out + ((size_t)(b * NPAT + c) * KNN + lane) * 3;
        dst[0] = p.x - cx;
        dst[1] = p.y - cy;
        dst[2] = p.z - cz;
    }
}

// ---------------------------------------------------------------------------
// Launch: prep -> fps -> knn (stream-ordered, graph-capturable, alloc-free)
// Output: tuple(patches, centers): [NB*NPAT*KNN*3] then [NB*NPAT*3]
// ---------------------------------------------------------------------------
extern "C" void kernel_launch(void* const* d_in, const int* in_sizes, int n_in,
                              void* d_out, int out_size) {
    const float* pts = (const float*)d_in[0];
    float* out      = (float*)d_out;
    float* patches  = out;                               // 16*64*32*3 = 98304
    float* centers  = out + (size_t)NB * NPAT * KNN * 3; // 16*64*3   =  3072

    prep_kernel<<<1024, 256>>>(pts);                     // 262144 threads = NB*NPTS/4
    fps_kernel<<<dim3(FPS_BLKS, NB), FPS_THR>>>(centers);
    knn_kernel<<<dim3(8, NB), 1024>>>(centers, patches);
}

// round 5
// speedup vs baseline: 1.1850x; 1.1850x over previous
#include <cuda_runtime.h>
#include <cuda_bf16.h>
#include <cstdint>

// Problem constants
#define NB   16
#define NPTS 65536
#define NPAT 64      // NUM_PATCHES
#define KNN  32      // PATCH_SIZE

// FPS decomposition: 8 blocks per batch, 1024 threads, 8 points per thread
#define FPS_BLKS   8
#define FPS_THR    1024
#define FPS_PPT    8

typedef unsigned long long u64;
typedef unsigned int u32;

// Scratch (allocation-free rule: __device__ globals; .bss = zero at load)
__device__ float4 g_pts4[NB * NPTS];             // x,y,z,|p|^2 (FMA-chain p2)
__device__ u64    g_part[NB * NPAT * FPS_BLKS];  // per-iter per-block argmax slot
                                                 // zeroed by knn_kernel for NEXT replay

// ---- acquire/release global u64 ----
__device__ __forceinline__ u64 ld_acq(const u64* p) {
    u64 v;
    asm volatile("ld.acquire.gpu.global.u64 %0, [%1];" : "=l"(v) : "l"(p) : "memory");
    return v;
}
__device__ __forceinline__ void st_rel(u64* p, u64 v) {
    asm volatile("st.release.gpu.global.u64 [%0], %1;" :: "l"(p), "l"(v) : "memory");
}

// ---------------------------------------------------------------------------
// Kernel 1: FPS (prep fused). One CTA per (batch, 1/8 slice). Each CTA:
//  - loads its 8192 raw points into registers, computes p2, writes g_pts4
//  - 64 iterations: local min_d update + argmax (exact round-2 arithmetic),
//    block reduce, publish block-best key to an L2 slot (st.release),
//    lanes 0-7 spin on the 8 slots in parallel (ld.acquire, NO nanosleep),
//    prefetch candidate coords during the key reduce, shfl-select winner.
// ---------------------------------------------------------------------------
__global__ void __launch_bounds__(FPS_THR, 1)
fps_kernel(const float* __restrict__ pts_raw,
           float* __restrict__ centers_out /* [NB][NPAT][3] */) {
    const int b    = blockIdx.y;
    const int sub  = blockIdx.x;          // 0..7
    const int tid  = threadIdx.x;
    const int lane = tid & 31;
    const int wid  = tid >> 5;            // 0..31

    const float* raw = pts_raw + (size_t)b * NPTS * 3;
    float4* pb4 = g_pts4 + (size_t)b * NPTS;
    const int gbase = sub * (NPTS / FPS_BLKS);   // 8192 per CTA

    // ---- fused prep: load slice, compute p2 (XLA shape), publish to g_pts4 ----
    float px[FPS_PPT], py[FPS_PPT], pz[FPS_PPT], md[FPS_PPT];
#pragma unroll
    for (int j = 0; j < FPS_PPT; j++) {
        int gi = gbase + j * FPS_THR + tid;
        float x = raw[3 * gi + 0];
        float y = raw[3 * gi + 1];
        float z = raw[3 * gi + 2];
        px[j] = x; py[j] = y; pz[j] = z;
        md[j] = 3.402823466e38f;   // finfo(float32).max
        float p2 = __fmaf_rn(z, z, __fmaf_rn(y, y, __fmul_rn(x, x)));
        pb4[gi] = make_float4(x, y, z, p2);
    }

    __shared__ float sc[4];
    __shared__ u64 wb[32];

    u64* part = g_part + (size_t)b * NPAT * FPS_BLKS;

    if (tid == 0) {   // deterministic start: point 0 (raw input, bit-exact)
        sc[0] = raw[0]; sc[1] = raw[1]; sc[2] = raw[2];
    }

    for (int iter = 0; iter < NPAT; iter++) {
        __syncthreads();   // sc valid; also orders g_pts4 STGs before publish
        float cx = sc[0], cy = sc[1], cz = sc[2];
        if (sub == 0 && tid == 0) {
            centers_out[(b * NPAT + iter) * 3 + 0] = cx;
            centers_out[(b * NPAT + iter) * 3 + 1] = cy;
            centers_out[(b * NPAT + iter) * 3 + 2] = cz;
        }
        if (iter == NPAT - 1) break;   // last winner never consumed

        // --- local update + argmax (exact: non-fused mul/add chain) ---
        float bestv = -1.0f;
        u32   besti = 0;
#pragma unroll
        for (int j = 0; j < FPS_PPT; j++) {
            float dx = px[j] - cx, dy = py[j] - cy, dz = pz[j] - cz;
            float d = __fadd_rn(__fadd_rn(__fmul_rn(dx, dx), __fmul_rn(dy, dy)), __fmul_rn(dz, dz));
            float m = fminf(md[j], d);
            md[j] = m;
            // strict > keeps earliest (lowest-gi) maximum, matching argmax
            if (m > bestv) { bestv = m; besti = (u32)(gbase + j * FPS_THR + tid); }
        }
        // key: (float bits, ~idx); md >= 0 so bits are order-preserving; key > 0
        u64 best = ((u64)__float_as_uint(bestv) << 32) | (u32)(~besti);
#pragma unroll
        for (int off = 16; off; off >>= 1) {
            u64 o = __shfl_xor_sync(0xffffffffu, best, off);
            if (o > best) best = o;
        }
        if (lane == 0) wb[wid] = best;
        __syncthreads();
        if (wid == 0) {
            u64 v = wb[lane];
#pragma unroll
            for (int off = 16; off; off >>= 1) {
                u64 o = __shfl_xor_sync(0xffffffffu, v, off);
                if (o > v) v = o;
            }
            // publish this block's partial (release: orders g_pts4 + key)
            if (lane == 0) st_rel(&part[iter * FPS_BLKS + sub], v);
            // lanes 0-7: parallel acquire-spin on the 8 slots
            if (lane < FPS_BLKS) {
                u64 s;
                while ((s = ld_acq(&part[iter * FPS_BLKS + lane])) == 0ull) {}
                u32 cand = ~(u32)s;
                float4 pc = pb4[cand];        // prefetch candidate coords
                u64 m = s;
#pragma unroll
                for (int off = 4; off; off >>= 1) {
                    u64 o = __shfl_xor_sync(0xffu, m, off);
                    if (o > m) m = o;
                }
                u32 bal = __ballot_sync(0xffu, s == m);
                int src = __ffs(bal) - 1;     // winner's poller lane
                float wx = __shfl_sync(0xffu, pc.x, src);
                float wy = __shfl_sync(0xffu, pc.y, src);
                float wz = __shfl_sync(0xffu, pc.z, src);
                if (lane == 0) { sc[0] = wx; sc[1] = wy; sc[2] = wz; }
            }
        }
    }
}

// ---------------------------------------------------------------------------
// Kernel 2: exact KNN top-32. 1024 threads = 32 warps = 8 centers x 4
// point-quarters. Gate processes 4 points/thread (128/warp) per iteration;
// accepts via O(1) sorted insertion (u64 keys, exact); bitonic fallback.
// Also zeroes g_part for the next graph replay.
// ---------------------------------------------------------------------------
__device__ __forceinline__ u64 bsort32(u64 v, int lane) {
#pragma unroll
    for (int k = 2; k <= 32; k <<= 1) {
#pragma unroll
        for (int j = k >> 1; j > 0; j >>= 1) {
            u64 o = __shfl_xor_sync(0xffffffffu, v, j);
            bool up      = ((lane & k) == 0);
            bool keepmin = (((lane & j) == 0) == up);
            bool smaller = (v < o);
            v = (smaller == keepmin) ? v : o;
        }
    }
    return v;
}
__device__ __forceinline__ u64 bmerge32(u64 v, int lane) {
#pragma unroll
    for (int j = 16; j > 0; j >>= 1) {
        u64 o = __shfl_xor_sync(0xffffffffu, v, j);
        bool keepmin = ((lane & j) == 0);
        bool smaller = (v < o);
        v = (smaller == keepmin) ? v : o;
    }
    return v;
}
__device__ __forceinline__ u32 flipf(float f) {
    u32 u = __float_as_uint(f);
    return u ^ ((u & 0x80000000u) ? 0xFFFFFFFFu : 0x80000000u);
}

#define KNN_CH 512           // points per quarter per chunk
#define QTR    (NPTS / 4)    // 16384

__global__ void __launch_bounds__(1024, 1)
knn_kernel(const float* __restrict__ centers /* [NB][NPAT][3] */,
           float* __restrict__ patches_out   /* [NB][NPAT][KNN][3] */) {
    const int b    = blockIdx.y;      // 16
    const int grp  = blockIdx.x;      // 8
    const int tid  = threadIdx.x;
    const int lane = tid & 31;
    const int w    = tid >> 5;        // 0..31
    const int cl   = w & 7;           // center within group
    const int q    = w >> 3;          // quarter 0..3
    const int c    = grp * 8 + cl;

    // zero FPS slots for the next replay (fps of this replay already done)
    {
        int gid = (b * 8 + grp) * 1024 + tid;
        if (gid < NB * NPAT * FPS_BLKS) g_part[gid] = 0ull;
    }

    const float4* pbase = g_pts4 + (size_t)b * NPTS;

    const float cx = centers[(b * NPAT + c) * 3 + 0];
    const float cy = centers[(b * NPAT + c) * 3 + 1];
    const float cz = centers[(b * NPAT + c) * 3 + 2];
    const float c2 = __fmaf_rn(cz, cz, __fmaf_rn(cy, cy, __fmul_rn(cx, cx)));

    u64 L = 0xFF80000000000000ull;              // key for d2=+inf, idx 0
    float curMax = __int_as_float(0x7f800000);  // +inf

    __shared__ float4 chunk[4 * KNN_CH];        // 32 KB
    __shared__ u64 smg[8][3][32];               // 6 KB quarter-merge buffers

    const int qbase = q * QTR;

    for (int cb = 0; cb < QTR; cb += KNN_CH) {
        __syncthreads();
        for (int t = tid; t < 4 * KNN_CH; t += 1024) {
            int qq = t >> 9;
            int off = t & (KNN_CH - 1);
            chunk[t] = pbase[qq * QTR + cb + off];
        }
        __syncthreads();

        const float4* my = chunk + q * KNN_CH;
#pragma unroll 1
        for (int i = 0; i < KNN_CH / 128; i++) {
            float4 pv[4];
            float d2[4];
#pragma unroll
            for (int k = 0; k < 4; k++) pv[k] = my[i * 128 + k * 32 + lane];
#pragma unroll
            for (int k = 0; k < 4; k++) {
                // XLA-shape d2: fma(-2, dot, c2+p2), dot = fma chain
                float dot = __fmaf_rn(pv[k].z, cz, __fmaf_rn(pv[k].y, cy, __fmul_rn(pv[k].x, cx)));
                d2[k] = __fmaf_rn(-2.0f, dot, __fadd_rn(c2, pv[k].w));
            }
            float mn = fminf(fminf(d2[0], d2[1]), fminf(d2[2], d2[3]));
            if (__any_sync(0xffffffffu, mn <= curMax)) {
#pragma unroll
                for (int k = 0; k < 4; k++) {
                    u32 mask = __ballot_sync(0xffffffffu, d2[k] <= curMax);
                    if (!mask) continue;
                    u32 gi = (u32)(qbase + cb + i * 128 + k * 32 + lane);
                    u64 cand = ((u64)flipf(d2[k]) << 32) | gi;
                    if (__popc(mask) <= 8) {
                        while (mask) {
                            int src = __ffs(mask) - 1; mask &= mask - 1;
                            u64 kk = __shfl_sync(0xffffffffu, cand, src);
                            u64 up = __shfl_up_sync(0xffffffffu, L, 1);
                            if (lane == 0) up = kk;
                            u64 mx = (kk > up) ? kk : up;
                            L = (L < kk) ? L : mx;
                        }
                    } else {
                        u64 cs = bsort32(cand, lane);
                        u64 o  = __shfl_sync(0xffffffffu, cs, 31 - lane);
                        u64 m  = (L < o) ? L : o;
                        L = bmerge32(m, lane);
                    }
                    u64 top = __shfl_sync(0xffffffffu, L, 31);
                    u32 th = (u32)(top >> 32);
                    th ^= (th & 0x80000000u) ? 0x80000000u : 0xFFFFFFFFu;
                    curMax = __uint_as_float(th);
                }
            }
        }
    }

    // merge 4 quarters per center: (1->0, 3->2), then (2->0)
    if (q == 1) { smg[cl][0][lane] = L; }
    if (q == 3) { smg[cl][1][lane] = L; }
    __syncthreads();
    if (q == 0) { u64 o = smg[cl][0][31 - lane]; u64 m = (L < o) ? L : o; L = bmerge32(m, lane); }
    if (q == 2) { u64 o = smg[cl][1][31 - lane]; u64 m = (L < o) ? L : o; L = bmerge32(m, lane); }
    __syncthreads();
    if (q == 2) { smg[cl][2][lane] = L; }
    __syncthreads();
    if (q == 0) {
        u64 o = smg[cl][2][31 - lane]; u64 m = (L < o) ? L : o; L = bmerge32(m, lane);
        // lane == rank k: gather + subtract center
        u32 gi = (u32)L;
        float4 p = pbase[gi];
        float* dst = patches_out + ((size_t)(b * NPAT + c) * KNN + lane) * 3;
        dst[0] = p.x - cx;
        dst[1] = p.y - cy;
        dst[2] = p.z - cz;
    }
}

// ---------------------------------------------------------------------------
// Launch: fps (prep fused) -> knn. Graph-capturable, alloc-free.
// Replay-safe: g_part zeroed at module load (.bss) and re-zeroed by knn
// at the end of every run for the next replay.
// Output: tuple(patches, centers): [NB*NPAT*KNN*3] then [NB*NPAT*3]
// ---------------------------------------------------------------------------
extern "C" void kernel_launch(void* const* d_in, const int* in_sizes, int n_in,
                              void* d_out, int out_size) {
    const float* pts = (const float*)d_in[0];
    float* out      = (float*)d_out;
    float* patches  = out;                               // 16*64*32*3 = 98304
    float* centers  = out + (size_t)NB * NPAT * KNN * 3; // 16*64*3   =  3072

    fps_kernel<<<dim3(FPS_BLKS, NB), FPS_THR>>>(pts, centers);
    knn_kernel<<<dim3(8, NB), 1024>>>(centers, patches);
}